// round 14
// baseline (speedup 1.0000x reference)
#include <cuda_runtime.h>
#include <cuda_fp16.h>
#include <math.h>
#include <cstdint>

// Problem constants
#define BS   8
#define TS   2048
#define NH   4
#define DIM  512
#define VDIM 512
#define QDIM 1024
#define KS   100
#define KN   100
#define TEMP 0.5f

#define MDIM (BS*TS)         // 16384 rows for K/V GEMMs
#define NKV  (NH*DIM)        // 2048
#define LROWS 384            // padded compact loc rows (302 used), batch-independent
#define MLOC (BS*LROWS)      // 3072 expanded rows

// ---------------- scratch (static device allocations) ----------------
__device__ float g_P[KN * (2*KS+2)];             // prefix sums [100][202]
__device__ float g_q[BS * NKV];                  // tanh(query) [8][2048]
__device__ float g_convr[LROWS * KN];            // batch-independent C [384][100]
__device__ float g_G[LROWS * DIM];               // G = C @ proj^T [384][512]
__device__ float g_locc[(size_t)MLOC * DIM];     // per-batch loc = tanh(G/len) [3072][512]
__device__ float g_energy[BS * NH * TS];         // raw energy partial sums
__device__ float g_ctx[BS * NH * VDIM];
__device__ __half g_Ah[(size_t)MDIM * VDIM];     // fp16 enc_feat
__device__ __half g_Bkh[NKV * VDIM];             // fp16 Wk
__device__ __half g_Bvh[NKV * VDIM];             // fp16 Wv

// ---------------- fast tanh: 1 - 2/(e^{2x}+1), abs err ~1.2e-7 ----------------
__device__ __forceinline__ float fast_tanh(float x) {
    float e;
    asm("ex2.approx.f32 %0, %1;" : "=f"(e) : "f"(x * 2.8853900817779268f)); // 2*log2(e)
    float r;
    asm("rcp.approx.f32 %0, %1;" : "=f"(r) : "f"(e + 1.0f));
    return fmaf(-2.0f, r, 1.0f);
}

// compact loc row index for timestep t given len
__device__ __forceinline__ int idx_t(int t, int len) {
    if (t < KS) return t;
    if (t <= len - KS - 1) return KS;
    int j = t - (len - KS);
    if (j < 2 * KS) return KS + 1 + j;   // 101..300
    return 301;                          // zero row
}

// ---------------- kernel: fp32 -> fp16 conversion ----------------
__global__ void f16_conv_kernel(const float4* __restrict__ in, __half2* __restrict__ outp, int n4) {
    int i = blockIdx.x * blockDim.x + threadIdx.x;
    if (i >= n4) return;
    float4 v = in[i];
    outp[2*i]   = __floats2half2_rn(v.x, v.y);
    outp[2*i+1] = __floats2half2_rn(v.z, v.w);
}

// ---------------- kernel 0: conv-weight prefix sums ----------------
__global__ void prefix_kernel(const float* __restrict__ w, float* __restrict__ P) {
    int k = threadIdx.x;
    if (k >= KN) return;
    float s = 0.0f;
    P[k * 202 + 0] = 0.0f;
    for (int t = 0; t < 2*KS+1; t++) {
        float ws = 0.0f;
        #pragma unroll
        for (int h = 0; h < NH; h++) ws += w[(k*NH + h)*(2*KS+1) + t];
        s += ws;
        P[k * 202 + t + 1] = s;
    }
}

// ---------------- kernel 1: query projection (float4 vectorized) ----------------
__global__ void query_kernel(const float* __restrict__ dec, const float* __restrict__ Wq,
                             const float* __restrict__ bq, float* __restrict__ q) {
    int gw = (blockIdx.x * blockDim.x + threadIdx.x) >> 5;
    int lane = threadIdx.x & 31;
    if (gw >= BS * NKV) return;
    int b = gw >> 11, n = gw & (NKV - 1);
    const float4* x4 = (const float4*)(dec + b * QDIM);
    const float4* w4 = (const float4*)(Wq + (size_t)n * QDIM);
    float acc = 0.0f;
    #pragma unroll
    for (int k = lane; k < QDIM / 4; k += 32) {
        float4 xv = __ldg(x4 + k);
        float4 wv = __ldg(w4 + k);
        acc += xv.x * wv.x + xv.y * wv.y + xv.z * wv.z + xv.w * wv.w;
    }
    #pragma unroll
    for (int o = 16; o; o >>= 1) acc += __shfl_xor_sync(0xffffffffu, acc, o);
    if (!lane) q[gw] = fast_tanh(acc + bq[n]);
}

// ---------------- kernel 2: batch-independent conv rows (+ zero init) ----------------
__global__ void convr_kernel(float* __restrict__ conv) {
    int idx = blockIdx.x * blockDim.x + threadIdx.x;
    if (idx < BS * NH * TS) g_energy[idx] = 0.0f;
    if (idx < BS * NH * VDIM) g_ctx[idx] = 0.0f;
    if (idx >= LROWS * KN) return;
    int k = idx % KN;
    int r = idx / KN;
    int lo, hi;
    if (r < KS)        { lo = KS - r; hi = 2*KS + 1; }
    else if (r == KS)  { lo = 0;      hi = 2*KS + 1; }
    else if (r <= 3*KS){ lo = 0;      hi = 2*KS - (r - KS - 1); }
    else               { conv[idx] = 0.0f; return; }
    conv[idx] = (hi > lo) ? (g_P[k*202 + hi] - g_P[k*202 + lo]) : 0.0f;
}

// ---------------- G GEMM: 64x64-tile fp32, raw output (K=100) ----------------
#define LBK 20
__global__ __launch_bounds__(256)
void gemm_raw64(const float* __restrict__ A, const float* __restrict__ B,
                float* __restrict__ C, int M, int N, int K) {
    __shared__ float As[LBK][68];
    __shared__ float Bs[LBK][68];
    int bm = blockIdx.y * 64;
    int bn = blockIdx.x * 64;
    int tid = threadIdx.x;
    int trow = (tid >> 4) * 4;
    int tcol = (tid & 15) * 4;
    float acc[4][4];
    #pragma unroll
    for (int i = 0; i < 4; i++)
        #pragma unroll
        for (int j = 0; j < 4; j++) acc[i][j] = 0.0f;

    for (int k0 = 0; k0 < K; k0 += LBK) {
        #pragma unroll
        for (int s = 0; s < 5; ++s) {
            int e = tid + s * 256;
            int row = e / LBK, kk = e % LBK;
            As[kk][row] = A[(size_t)(bm + row) * K + k0 + kk];
            Bs[kk][row] = B[(size_t)(bn + row) * K + k0 + kk];
        }
        __syncthreads();
        #pragma unroll
        for (int kk = 0; kk < LBK; kk++) {
            float ra[4], rb[4];
            #pragma unroll
            for (int i = 0; i < 4; i++) ra[i] = As[kk][trow + i];
            #pragma unroll
            for (int j = 0; j < 4; j++) rb[j] = Bs[kk][tcol + j];
            #pragma unroll
            for (int i = 0; i < 4; i++)
                #pragma unroll
                for (int j = 0; j < 4; j++) acc[i][j] += ra[i] * rb[j];
        }
        __syncthreads();
    }

    #pragma unroll
    for (int i = 0; i < 4; i++) {
        size_t off = (size_t)(bm + trow + i) * N + bn + tcol;
        #pragma unroll
        for (int j = 0; j < 4; j++)
            C[off + j] = acc[i][j];
    }
}

// ---------------- expand: loc[b,r,d] = tanh(G[r,d]/len_b) ----------------
__global__ void loc_expand_kernel(const int* __restrict__ enc_len) {
    int idx = blockIdx.x * blockDim.x + threadIdx.x;   // one float4
    const int per_b = LROWS * DIM / 4;                 // 49152
    if (idx >= BS * per_b) return;
    int b = idx / per_b;
    int rd = idx - b * per_b;
    float invlen = 1.0f / (float)enc_len[b];
    float4 g = ((const float4*)g_G)[rd];
    float4 o;
    o.x = fast_tanh(g.x * invlen);
    o.y = fast_tanh(g.y * invlen);
    o.z = fast_tanh(g.z * invlen);
    o.w = fast_tanh(g.w * invlen);
    ((float4*)g_locc)[(size_t)b * per_b + rd] = o;
}

// ================= fp16 mma GEMM core macros (R10 proven config) =================
#define GSTAGES 3
#define BKK     32
#define PADH    40                        // halfs per smem row (80 B pitch)
#define ATILE_H (128 * PADH)
#define STAGE_H (2 * ATILE_H)
#define GSMEM_BYTES (GSTAGES * STAGE_H * 2)   // 61440 B

__device__ __forceinline__ void mma_f16(float* d,
                                        uint32_t a0, uint32_t a1, uint32_t a2, uint32_t a3,
                                        uint32_t b0, uint32_t b1) {
    asm volatile(
        "mma.sync.aligned.m16n8k16.row.col.f32.f16.f16.f32 "
        "{%0,%1,%2,%3}, {%4,%5,%6,%7}, {%8,%9}, {%0,%1,%2,%3};"
        : "+f"(d[0]), "+f"(d[1]), "+f"(d[2]), "+f"(d[3])
        : "r"(a0), "r"(a1), "r"(a2), "r"(a3), "r"(b0), "r"(b1));
}
__device__ __forceinline__ void cp_async16(uint32_t saddr, const void* gaddr) {
    asm volatile("cp.async.cg.shared.global [%0], [%1], 16;" :: "r"(saddr), "l"(gaddr) : "memory");
}
__device__ __forceinline__ uint32_t smem_u32(const void* p) {
    uint32_t a;
    asm("{ .reg .u64 t; cvta.to.shared.u64 t, %1; cvt.u32.u64 %0, t; }" : "=r"(a) : "l"(p));
    return a;
}
__device__ __forceinline__ void ldsm_x4(uint32_t& r0, uint32_t& r1, uint32_t& r2, uint32_t& r3,
                                        uint32_t addr) {
    asm volatile("ldmatrix.sync.aligned.m8n8.x4.shared.b16 {%0,%1,%2,%3}, [%4];"
                 : "=r"(r0), "=r"(r1), "=r"(r2), "=r"(r3) : "r"(addr));
}
__device__ __forceinline__ void ldsm_x2(uint32_t& r0, uint32_t& r1, uint32_t addr) {
    asm volatile("ldmatrix.sync.aligned.m8n8.x2.shared.b16 {%0,%1}, [%2];"
                 : "=r"(r0), "=r"(r1) : "r"(addr));
}

// mainloop shared by both fused GEMMs; leaves acc[4][4][4] filled.
#define GEMM_MAINLOOP(A, B, K)                                                         \
    const int tid = threadIdx.x;                                                       \
    const int wid = tid >> 5, lane = tid & 31;                                         \
    const int wm = wid & 1, wn = wid >> 1;                                             \
    const int tr = lane >> 2, tc = lane & 3;                                           \
    const int bm = blockIdx.y * 128, bn = blockIdx.x * 128;                            \
    const int NT = (K) / BKK;                                                          \
    const uint32_t smb = smem_u32(smh);                                                \
    const int aRow = wm * 64 + (lane & 7) + ((lane >> 3) & 1) * 8;                     \
    const int aKh  = (lane >> 4) * 8;                                                  \
    const uint32_t aBase = smb + aRow * (PADH * 2) + aKh * 2;                          \
    const int lB   = lane & 15;                                                        \
    const int bRow = wn * 32 + (lB & 7);                                               \
    const int bKh  = (lB >> 3) * 8;                                                    \
    const uint32_t bBase = smb + ATILE_H * 2 + bRow * (PADH * 2) + bKh * 2;            \
    float acc[4][4][4];                                                                \
    _Pragma("unroll") for (int mt = 0; mt < 4; mt++)                                   \
        _Pragma("unroll") for (int nt = 0; nt < 4; nt++)                               \
            _Pragma("unroll") for (int r = 0; r < 4; r++) acc[mt][nt][r] = 0.0f;       \
    _Pragma("unroll") for (int s = 0; s < GSTAGES - 1; ++s) {                          \
        uint32_t sa = smb + s * (STAGE_H * 2);                                         \
        uint32_t sb = sa + ATILE_H * 2;                                                \
        int kbase = s * BKK;                                                           \
        _Pragma("unroll") for (int j = 0; j < 2; ++j) {                                \
            int c = tid + j * 256;                                                     \
            int row = c >> 2, kc = c & 3;                                              \
            uint32_t soff = row * (PADH * 2) + kc * 16;                                \
            cp_async16(sa + soff, (A) + (size_t)(bm + row) * (K) + kbase + kc * 8);    \
            cp_async16(sb + soff, (B) + (size_t)(bn + row) * (K) + kbase + kc * 8);    \
        }                                                                              \
        asm volatile("cp.async.commit_group;" ::: "memory");                           \
    }                                                                                  \
    for (int kt = 0; kt < NT; ++kt) {                                                  \
        asm volatile("cp.async.wait_group %0;" :: "n"(GSTAGES - 2) : "memory");        \
        __syncthreads();                                                               \
        {                                                                              \
            int tl = kt + GSTAGES - 1;                                                 \
            if (tl < NT) {                                                             \
                int s = tl % GSTAGES;                                                  \
                uint32_t sa = smb + s * (STAGE_H * 2);                                 \
                uint32_t sb = sa + ATILE_H * 2;                                        \
                int kbase = tl * BKK;                                                  \
                _Pragma("unroll") for (int j = 0; j < 2; ++j) {                        \
                    int c = tid + j * 256;                                             \
                    int row = c >> 2, kc = c & 3;                                      \
                    uint32_t soff = row * (PADH * 2) + kc * 16;                        \
                    cp_async16(sa + soff, (A) + (size_t)(bm + row) * (K) + kbase + kc * 8); \
                    cp_async16(sb + soff, (B) + (size_t)(bn + row) * (K) + kbase + kc * 8); \
                }                                                                      \
            }                                                                          \
            asm volatile("cp.async.commit_group;" ::: "memory");                       \
        }                                                                              \
        const uint32_t stOff = (uint32_t)(kt % GSTAGES) * (STAGE_H * 2);               \
        _Pragma("unroll") for (int ks = 0; ks < 2; ++ks) {                             \
            uint32_t af[4][4];                                                         \
            _Pragma("unroll") for (int mt = 0; mt < 4; mt++)                           \
                ldsm_x4(af[mt][0], af[mt][1], af[mt][2], af[mt][3],                    \
                        aBase + stOff + mt * (16 * PADH * 2) + ks * 32);               \
            uint32_t bf[4][2];                                                         \
            _Pragma("unroll") for (int nt = 0; nt < 4; nt++)                           \
                ldsm_x2(bf[nt][0], bf[nt][1],                                          \
                        bBase + stOff + nt * (8 * PADH * 2) + ks * 32);                \
            _Pragma("unroll") for (int mt = 0; mt < 4; mt++)                           \
                _Pragma("unroll") for (int nt = 0; nt < 4; nt++)                       \
                    mma_f16(acc[mt][nt], af[mt][0], af[mt][1], af[mt][2], af[mt][3],   \
                            bf[nt][0], bf[nt][1]);                                     \
        }                                                                              \
        __syncthreads();                                                               \
    }

// ---------------- key GEMM + fused energy (skips fully-masked tiles) ----------------
__global__ __launch_bounds__(256, 2)
void gemm_key_energy(const __half* __restrict__ A, const __half* __restrict__ B,
                     const float* __restrict__ bias, const float* __restrict__ q,
                     const float* __restrict__ gen_w, const int* __restrict__ enc_len) {
    extern __shared__ __half smh[];
    {
        int b0 = (int)(blockIdx.y >> 4);
        int t0 = (int)(blockIdx.y & 15) * 128;
        if (t0 >= enc_len[b0]) return;
    }
    GEMM_MAINLOOP(A, B, VDIM)

    const int b = bm >> 11;
    const int len = enc_len[b];
    const int h = bn >> 9;
    const int dbase = (bn & 511) + wn * 32;

    float qv[8], wv[8], bv8[8];
    #pragma unroll
    for (int nt = 0; nt < 4; nt++)
        #pragma unroll
        for (int u = 0; u < 2; u++) {
            int d = dbase + nt * 8 + tc * 2 + u;
            int n = (h << 9) + d;
            qv[nt*2+u]  = __ldg(q + b * NKV + n);
            wv[nt*2+u]  = __ldg(gen_w + d);
            bv8[nt*2+u] = __ldg(bias + n);
        }

    float rowsum[8];
    #pragma unroll
    for (int i = 0; i < 8; i++) rowsum[i] = 0.0f;

    #pragma unroll
    for (int mt = 0; mt < 4; mt++) {
        #pragma unroll
        for (int half = 0; half < 2; half++) {
            int r = bm + wm * 64 + mt * 16 + tr + half * 8;
            int t = r & (TS - 1);
            const float* locp = g_locc + (size_t)(b * LROWS + idx_t(t, len)) * DIM + dbase;
            float s = 0.0f;
            #pragma unroll
            for (int nt = 0; nt < 4; nt++)
                #pragma unroll
                for (int u = 0; u < 2; u++) {
                    float kk = fast_tanh(acc[mt][nt][half*2+u] + bv8[nt*2+u]);
                    float lv = locp[nt * 8 + tc * 2 + u];
                    s += wv[nt*2+u] * fast_tanh(kk + qv[nt*2+u] + lv);
                }
            rowsum[mt*2+half] = s;
        }
    }
    #pragma unroll
    for (int i = 0; i < 8; i++) {
        rowsum[i] += __shfl_xor_sync(0xffffffffu, rowsum[i], 1);
        rowsum[i] += __shfl_xor_sync(0xffffffffu, rowsum[i], 2);
    }
    if (tc == 0) {
        #pragma unroll
        for (int mt = 0; mt < 4; mt++)
            #pragma unroll
            for (int half = 0; half < 2; half++) {
                int r = bm + wm * 64 + mt * 16 + tr + half * 8;
                int t = r & (TS - 1);
                atomicAdd(&g_energy[(b * NH + h) * TS + t], rowsum[mt*2+half]);
            }
    }
}

// ---------------- value GEMM + fused context (self-computed softmax stats) ----------------
__global__ __launch_bounds__(256, 2)
void gemm_val_ctx(const __half* __restrict__ A, const __half* __restrict__ B,
                  const float* __restrict__ bias, const float* __restrict__ gen_b,
                  const int* __restrict__ enc_len) {
    extern __shared__ __half smh[];
    {
        int b0 = (int)(blockIdx.y >> 4);
        int t0 = (int)(blockIdx.y & 15) * 128;
        if (t0 >= enc_len[b0]) return;
    }
    GEMM_MAINLOOP(A, B, VDIM)

    const int b = bm >> 11;
    const int len = enc_len[b];
    const int h = bn >> 9;
    const int dbase = (bn & 511) + wn * 32;

    // ---- per-CTA softmax stats for this (b,h) row (recomputed from energy) ----
    float* sred = (float*)smh;   // reuse pipeline smem (all threads past mainloop)
    const float* erow = g_energy + (b * NH + h) * TS;
    const float gb = __ldg(gen_b);
    float lm = -INFINITY;
    for (int t = tid; t < len; t += 256)
        lm = fmaxf(lm, (erow[t] + gb) * (1.0f / TEMP));
    #pragma unroll
    for (int o = 16; o; o >>= 1) lm = fmaxf(lm, __shfl_xor_sync(0xffffffffu, lm, o));
    __syncthreads();
    if (!lane) sred[wid] = lm;
    __syncthreads();
    float m8 = sred[0];
    #pragma unroll
    for (int i = 1; i < 8; i++) m8 = fmaxf(m8, sred[i]);
    const float mstat = m8;
    __syncthreads();

    float lsum = 0.0f;
    for (int t = tid; t < len; t += 256)
        lsum += expf((erow[t] + gb) * (1.0f / TEMP) - mstat);
    #pragma unroll
    for (int o = 16; o; o >>= 1) lsum += __shfl_xor_sync(0xffffffffu, lsum, o);
    __syncthreads();
    if (!lane) sred[wid] = lsum;
    __syncthreads();
    float s8 = 0.0f;
    #pragma unroll
    for (int i = 0; i < 8; i++) s8 += sred[i];
    const float invZ = 1.0f / s8;

    float bv8[8];
    #pragma unroll
    for (int nt = 0; nt < 4; nt++)
        #pragma unroll
        for (int u = 0; u < 2; u++)
            bv8[nt*2+u] = __ldg(bias + (h << 9) + dbase + nt * 8 + tc * 2 + u);

    float colsum[8];
    #pragma unroll
    for (int i = 0; i < 8; i++) colsum[i] = 0.0f;

    #pragma unroll
    for (int mt = 0; mt < 4; mt++) {
        #pragma unroll
        for (int half = 0; half < 2; half++) {
            int r = bm + wm * 64 + mt * 16 + tr + half * 8;
            int t = r & (TS - 1);
            float a_t = (t < len)
                ? expf((erow[t] + gb) * (1.0f / TEMP) - mstat) * invZ : 0.0f;
            #pragma unroll
            for (int nt = 0; nt < 4; nt++)
                #pragma unroll
                for (int u = 0; u < 2; u++)
                    colsum[nt*2+u] += a_t * fast_tanh(acc[mt][nt][half*2+u] + bv8[nt*2+u]);
        }
    }
    #pragma unroll
    for (int i = 0; i < 8; i++) {
        colsum[i] += __shfl_xor_sync(0xffffffffu, colsum[i], 4);
        colsum[i] += __shfl_xor_sync(0xffffffffu, colsum[i], 8);
        colsum[i] += __shfl_xor_sync(0xffffffffu, colsum[i], 16);
    }
    if (tr == 0) {
        #pragma unroll
        for (int nt = 0; nt < 4; nt++)
            #pragma unroll
            for (int u = 0; u < 2; u++)
                atomicAdd(&g_ctx[(b * NH + h) * VDIM + dbase + nt * 8 + tc * 2 + u],
                          colsum[nt*2+u]);
    }
}

// ---------------- masked softmax -> out_attn (runs concurrent with value GEMM) ----------------
__global__ void softmax_kernel(const int* __restrict__ enc_len, float* __restrict__ attn,
                               const float* __restrict__ gen_b) {
    __shared__ float red[8];
    __shared__ float bcast;
    int bh = blockIdx.x;
    int b = bh >> 2;
    int len = enc_len[b];
    float gb = gen_b[0];
    const float* e = g_energy + bh * TS;
    float* a = attn + bh * TS;
    int tid = threadIdx.x, lane = tid & 31, w = tid >> 5;

    float m = -INFINITY;
    for (int t = tid; t < len; t += 256) m = fmaxf(m, (e[t] + gb) * (1.0f / TEMP));
    #pragma unroll
    for (int o = 16; o; o >>= 1) m = fmaxf(m, __shfl_xor_sync(0xffffffffu, m, o));
    if (!lane) red[w] = m;
    __syncthreads();
    if (tid < 8) {
        float x = red[tid];
        #pragma unroll
        for (int o = 4; o; o >>= 1) x = fmaxf(x, __shfl_xor_sync(0xffu, x, o));
        if (!tid) bcast = x;
    }
    __syncthreads();
    m = bcast;
    __syncthreads();

    float s = 0.0f;
    for (int t = tid; t < len; t += 256) s += expf((e[t] + gb) * (1.0f / TEMP) - m);
    #pragma unroll
    for (int o = 16; o; o >>= 1) s += __shfl_xor_sync(0xffffffffu, s, o);
    if (!lane) red[w] = s;
    __syncthreads();
    if (tid < 8) {
        float x = red[tid];
        #pragma unroll
        for (int o = 4; o; o >>= 1) x += __shfl_xor_sync(0xffu, x, o);
        if (!tid) bcast = x;
    }
    __syncthreads();
    float inv = 1.0f / bcast;
    for (int t = tid; t < TS; t += 256)
        a[t] = (t < len) ? expf((e[t] + gb) * (1.0f / TEMP) - m) * inv : 0.0f;
}

// ---------------- merge projection ----------------
__global__ void merge_kernel(const float* __restrict__ Wm, const float* __restrict__ bm,
                             float* __restrict__ out) {
    int gw = (blockIdx.x * blockDim.x + threadIdx.x) >> 5;
    int lane = threadIdx.x & 31;
    if (gw >= BS * VDIM) return;
    int b = gw >> 9, j = gw & (VDIM - 1);
    const float* x = g_ctx + b * (NH * VDIM);
    const float* w = Wm + (size_t)j * (NH * VDIM);
    float acc = 0.0f;
    for (int k = lane; k < NH * VDIM; k += 32) acc += x[k] * w[k];
    #pragma unroll
    for (int o = 16; o; o >>= 1) acc += __shfl_xor_sync(0xffffffffu, acc, o);
    if (!lane) out[gw] = acc + bm[j];
}

// ---------------- launch ----------------
extern "C" void kernel_launch(void* const* d_in, const int* in_sizes, int n_in,
                              void* d_out, int out_size) {
    const float* dec_state  = (const float*)d_in[0];
    const float* enc_feat   = (const float*)d_in[1];
    const int*   enc_len    = (const int*)  d_in[2];
    const float* Wq         = (const float*)d_in[3];
    const float* bq         = (const float*)d_in[4];
    const float* Wk         = (const float*)d_in[5];
    const float* bk         = (const float*)d_in[6];
    const float* Wv         = (const float*)d_in[7];
    const float* bv         = (const float*)d_in[8];
    const float* loc_conv_w = (const float*)d_in[9];
    const float* loc_proj_w = (const float*)d_in[10];
    const float* gen_w      = (const float*)d_in[11];
    const float* gen_b      = (const float*)d_in[12];
    const float* merge_w    = (const float*)d_in[13];
    const float* merge_b    = (const float*)d_in[14];

    float* out = (float*)d_out;
    float* out_attn = out;                       // [8,4,2048]
    float* out_ctx  = out + BS * NH * TS;        // [8,512]

    static float *pP = nullptr, *pQ = nullptr, *pConvr = nullptr, *pG = nullptr;
    static __half *pAh = nullptr, *pBkh = nullptr, *pBvh = nullptr;
    static cudaStream_t sB = nullptr, sC = nullptr;
    static cudaEvent_t evRoot = nullptr, evB1 = nullptr, evB2 = nullptr, evC = nullptr,
                      evKey = nullptr, evSM = nullptr;
    if (!pP) {
        cudaGetSymbolAddress((void**)&pP,     g_P);
        cudaGetSymbolAddress((void**)&pQ,     g_q);
        cudaGetSymbolAddress((void**)&pConvr, g_convr);
        cudaGetSymbolAddress((void**)&pG,     g_G);
        cudaGetSymbolAddress((void**)&pAh,    g_Ah);
        cudaGetSymbolAddress((void**)&pBkh,   g_Bkh);
        cudaGetSymbolAddress((void**)&pBvh,   g_Bvh);
        cudaFuncSetAttribute(gemm_key_energy, cudaFuncAttributeMaxDynamicSharedMemorySize, GSMEM_BYTES);
        cudaFuncSetAttribute(gemm_val_ctx,    cudaFuncAttributeMaxDynamicSharedMemorySize, GSMEM_BYTES);
        cudaStreamCreateWithFlags(&sB, cudaStreamNonBlocking);
        cudaStreamCreateWithFlags(&sC, cudaStreamNonBlocking);
        cudaEventCreateWithFlags(&evRoot, cudaEventDisableTiming);
        cudaEventCreateWithFlags(&evB1, cudaEventDisableTiming);
        cudaEventCreateWithFlags(&evB2, cudaEventDisableTiming);
        cudaEventCreateWithFlags(&evC, cudaEventDisableTiming);
        cudaEventCreateWithFlags(&evKey, cudaEventDisableTiming);
        cudaEventCreateWithFlags(&evSM, cudaEventDisableTiming);
    }

    // ---- fork: three independent prologue branches ----
    cudaEventRecord(evRoot, 0);
    cudaStreamWaitEvent(sB, evRoot, 0);
    cudaStreamWaitEvent(sC, evRoot, 0);

    // branch B (sB): A conversion -> Wk conversion -> evB1 -> Wv conversion -> evB2
    {
        int nA4 = MDIM * VDIM / 4;
        f16_conv_kernel<<<(nA4 + 255) / 256, 256, 0, sB>>>((const float4*)enc_feat, (__half2*)pAh, nA4);
        int nB4 = NKV * VDIM / 4;
        f16_conv_kernel<<<(nB4 + 255) / 256, 256, 0, sB>>>((const float4*)Wk, (__half2*)pBkh, nB4);
        cudaEventRecord(evB1, sB);
        f16_conv_kernel<<<(nB4 + 255) / 256, 256, 0, sB>>>((const float4*)Wv, (__half2*)pBvh, nB4);
        cudaEventRecord(evB2, sB);
    }

    // branch C (sC): query projection
    {
        query_kernel<<<(BS * NKV * 32 + 255) / 256, 256, 0, sC>>>(dec_state, Wq, bq, pQ);
        cudaEventRecord(evC, sC);
    }

    // main stream: loc path (prefix -> batch-indep conv + zero -> G GEMM -> expand)
    prefix_kernel<<<1, 128>>>(loc_conv_w, pP);
    convr_kernel<<<(BS * NH * TS + 255) / 256, 256>>>(pConvr);
    {
        dim3 gl(DIM / 64, LROWS / 64);
        gemm_raw64<<<gl, 256>>>(pConvr, loc_proj_w, pG, LROWS, DIM, KN);
    }
    loc_expand_kernel<<<(BS * LROWS * DIM / 4 + 255) / 256, 256>>>(enc_len);

    // ---- join for key GEMM (needs A, Wk, q, loc) ----
    cudaStreamWaitEvent(0, evB1, 0);
    cudaStreamWaitEvent(0, evC, 0);
    {
        dim3 gk(NKV / 128, MDIM / 128);
        gemm_key_energy<<<gk, 256, GSMEM_BYTES>>>(pAh, pBkh, bk, pQ, gen_w, enc_len);
    }
    cudaEventRecord(evKey, 0);

    // softmax -> out_attn on side stream, CONCURRENT with value GEMM
    cudaStreamWaitEvent(sC, evKey, 0);
    softmax_kernel<<<BS * NH, 256, 0, sC>>>(enc_len, out_attn, gen_b);
    cudaEventRecord(evSM, sC);

    // value GEMM (self-computed softmax stats; needs energy + Wv only)
    cudaStreamWaitEvent(0, evB2, 0);
    {
        dim3 gk(NKV / 128, MDIM / 128);
        gemm_val_ctx<<<gk, 256, GSMEM_BYTES>>>(pAh, pBvh, bv, gen_b, enc_len);
    }

    // merge (does not need attn)
    merge_kernel<<<(BS * VDIM * 32 + 255) / 256, 256>>>(merge_w, merge_b, out_ctx);

    // join softmax before graph end so out_attn is complete
    cudaStreamWaitEvent(0, evSM, 0);
}

// round 15
// speedup vs baseline: 1.0376x; 1.0376x over previous
#include <cuda_runtime.h>
#include <cuda_fp16.h>
#include <math.h>
#include <cstdint>

// Problem constants
#define BS   8
#define TS   2048
#define NH   4
#define DIM  512
#define VDIM 512
#define QDIM 1024
#define KS   100
#define KN   100
#define TEMP 0.5f

#define MDIM (BS*TS)         // 16384 rows for K/V GEMMs
#define NKV  (NH*DIM)        // 2048
#define LROWS 384            // padded compact loc rows (302 used), batch-independent
#define MLOC (BS*LROWS)      // 3072 expanded rows

// ---------------- scratch (static device allocations) ----------------
__device__ float g_P[KN * (2*KS+2)];             // prefix sums [100][202]
__device__ float g_q[BS * NKV];                  // tanh(query) [8][2048]
__device__ float g_convr[LROWS * KN];            // batch-independent C [384][100]
__device__ float g_G[LROWS * DIM];               // G = C @ proj^T [384][512]
__device__ float g_locc[(size_t)MLOC * DIM];     // per-batch loc = tanh(G/len) [3072][512]
__device__ float g_energy[BS * NH * TS];         // raw energy partial sums
__device__ float g_ctx[BS * NH * VDIM];
__device__ __half g_Ah[(size_t)MDIM * VDIM];     // fp16 enc_feat
__device__ __half g_Bkh[NKV * VDIM];             // fp16 Wk
__device__ __half g_Bvh[NKV * VDIM];             // fp16 Wv

// ---------------- fast tanh: 1 - 2/(e^{2x}+1), abs err ~1.2e-7 ----------------
__device__ __forceinline__ float fast_tanh(float x) {
    float e;
    asm("ex2.approx.f32 %0, %1;" : "=f"(e) : "f"(x * 2.8853900817779268f)); // 2*log2(e)
    float r;
    asm("rcp.approx.f32 %0, %1;" : "=f"(r) : "f"(e + 1.0f));
    return fmaf(-2.0f, r, 1.0f);
}

// compact loc row index for timestep t given len
__device__ __forceinline__ int idx_t(int t, int len) {
    if (t < KS) return t;
    if (t <= len - KS - 1) return KS;
    int j = t - (len - KS);
    if (j < 2 * KS) return KS + 1 + j;   // 101..300
    return 301;                          // zero row
}

// ---------------- kernel: fp32 -> fp16 conversion ----------------
__global__ void f16_conv_kernel(const float4* __restrict__ in, __half2* __restrict__ outp, int n4) {
    int i = blockIdx.x * blockDim.x + threadIdx.x;
    if (i >= n4) return;
    float4 v = in[i];
    outp[2*i]   = __floats2half2_rn(v.x, v.y);
    outp[2*i+1] = __floats2half2_rn(v.z, v.w);
}

// ---------------- kernel 0: conv-weight prefix sums ----------------
__global__ void prefix_kernel(const float* __restrict__ w, float* __restrict__ P) {
    int k = threadIdx.x;
    if (k >= KN) return;
    float s = 0.0f;
    P[k * 202 + 0] = 0.0f;
    for (int t = 0; t < 2*KS+1; t++) {
        float ws = 0.0f;
        #pragma unroll
        for (int h = 0; h < NH; h++) ws += w[(k*NH + h)*(2*KS+1) + t];
        s += ws;
        P[k * 202 + t + 1] = s;
    }
}

// ---------------- kernel 1: query projection ----------------
__global__ void query_kernel(const float* __restrict__ dec, const float* __restrict__ Wq,
                             const float* __restrict__ bq, float* __restrict__ q) {
    int gw = (blockIdx.x * blockDim.x + threadIdx.x) >> 5;
    int lane = threadIdx.x & 31;
    if (gw >= BS * NKV) return;
    int b = gw >> 11, n = gw & (NKV - 1);
    const float* x = dec + b * QDIM;
    const float* w = Wq + (size_t)n * QDIM;
    float acc = 0.0f;
    for (int k = lane; k < QDIM; k += 32) acc += x[k] * w[k];
    #pragma unroll
    for (int o = 16; o; o >>= 1) acc += __shfl_xor_sync(0xffffffffu, acc, o);
    if (!lane) q[gw] = fast_tanh(acc + bq[n]);
}

// ---------------- kernel 2: batch-independent conv rows (+ zero init) ----------------
__global__ void convr_kernel(float* __restrict__ conv) {
    int idx = blockIdx.x * blockDim.x + threadIdx.x;
    if (idx < BS * NH * TS) g_energy[idx] = 0.0f;
    if (idx < BS * NH * VDIM) g_ctx[idx] = 0.0f;
    if (idx >= LROWS * KN) return;
    int k = idx % KN;
    int r = idx / KN;
    int lo, hi;
    if (r < KS)        { lo = KS - r; hi = 2*KS + 1; }
    else if (r == KS)  { lo = 0;      hi = 2*KS + 1; }
    else if (r <= 3*KS){ lo = 0;      hi = 2*KS - (r - KS - 1); }
    else               { conv[idx] = 0.0f; return; }
    conv[idx] = (hi > lo) ? (g_P[k*202 + hi] - g_P[k*202 + lo]) : 0.0f;
}

// ---------------- G GEMM: 64x64-tile fp32, raw output (K=100) ----------------
#define LBK 20
__global__ __launch_bounds__(256)
void gemm_raw64(const float* __restrict__ A, const float* __restrict__ B,
                float* __restrict__ C, int M, int N, int K) {
    __shared__ float As[LBK][68];
    __shared__ float Bs[LBK][68];
    int bm = blockIdx.y * 64;
    int bn = blockIdx.x * 64;
    int tid = threadIdx.x;
    int trow = (tid >> 4) * 4;
    int tcol = (tid & 15) * 4;
    float acc[4][4];
    #pragma unroll
    for (int i = 0; i < 4; i++)
        #pragma unroll
        for (int j = 0; j < 4; j++) acc[i][j] = 0.0f;

    for (int k0 = 0; k0 < K; k0 += LBK) {
        #pragma unroll
        for (int s = 0; s < 5; ++s) {
            int e = tid + s * 256;
            int row = e / LBK, kk = e % LBK;
            As[kk][row] = A[(size_t)(bm + row) * K + k0 + kk];
            Bs[kk][row] = B[(size_t)(bn + row) * K + k0 + kk];
        }
        __syncthreads();
        #pragma unroll
        for (int kk = 0; kk < LBK; kk++) {
            float ra[4], rb[4];
            #pragma unroll
            for (int i = 0; i < 4; i++) ra[i] = As[kk][trow + i];
            #pragma unroll
            for (int j = 0; j < 4; j++) rb[j] = Bs[kk][tcol + j];
            #pragma unroll
            for (int i = 0; i < 4; i++)
                #pragma unroll
                for (int j = 0; j < 4; j++) acc[i][j] += ra[i] * rb[j];
        }
        __syncthreads();
    }

    #pragma unroll
    for (int i = 0; i < 4; i++) {
        size_t off = (size_t)(bm + trow + i) * N + bn + tcol;
        #pragma unroll
        for (int j = 0; j < 4; j++)
            C[off + j] = acc[i][j];
    }
}

// ---------------- expand: loc[b,r,d] = tanh(G[r,d]/len_b) ----------------
__global__ void loc_expand_kernel(const int* __restrict__ enc_len) {
    int idx = blockIdx.x * blockDim.x + threadIdx.x;   // one float4
    const int per_b = LROWS * DIM / 4;                 // 49152
    if (idx >= BS * per_b) return;
    int b = idx / per_b;
    int rd = idx - b * per_b;
    float invlen = 1.0f / (float)enc_len[b];
    float4 g = ((const float4*)g_G)[rd];
    float4 o;
    o.x = fast_tanh(g.x * invlen);
    o.y = fast_tanh(g.y * invlen);
    o.z = fast_tanh(g.z * invlen);
    o.w = fast_tanh(g.w * invlen);
    ((float4*)g_locc)[(size_t)b * per_b + rd] = o;
}

// ================= fp16 mma GEMM core macros (R10 proven config) =================
#define GSTAGES 3
#define BKK     32
#define PADH    40                        // halfs per smem row (80 B pitch)
#define ATILE_H (128 * PADH)
#define STAGE_H (2 * ATILE_H)
#define GSMEM_BYTES (GSTAGES * STAGE_H * 2)   // 61440 B

__device__ __forceinline__ void mma_f16(float* d,
                                        uint32_t a0, uint32_t a1, uint32_t a2, uint32_t a3,
                                        uint32_t b0, uint32_t b1) {
    asm volatile(
        "mma.sync.aligned.m16n8k16.row.col.f32.f16.f16.f32 "
        "{%0,%1,%2,%3}, {%4,%5,%6,%7}, {%8,%9}, {%0,%1,%2,%3};"
        : "+f"(d[0]), "+f"(d[1]), "+f"(d[2]), "+f"(d[3])
        : "r"(a0), "r"(a1), "r"(a2), "r"(a3), "r"(b0), "r"(b1));
}
__device__ __forceinline__ void cp_async16(uint32_t saddr, const void* gaddr) {
    asm volatile("cp.async.cg.shared.global [%0], [%1], 16;" :: "r"(saddr), "l"(gaddr) : "memory");
}
__device__ __forceinline__ uint32_t smem_u32(const void* p) {
    uint32_t a;
    asm("{ .reg .u64 t; cvta.to.shared.u64 t, %1; cvt.u32.u64 %0, t; }" : "=r"(a) : "l"(p));
    return a;
}
__device__ __forceinline__ void ldsm_x4(uint32_t& r0, uint32_t& r1, uint32_t& r2, uint32_t& r3,
                                        uint32_t addr) {
    asm volatile("ldmatrix.sync.aligned.m8n8.x4.shared.b16 {%0,%1,%2,%3}, [%4];"
                 : "=r"(r0), "=r"(r1), "=r"(r2), "=r"(r3) : "r"(addr));
}
__device__ __forceinline__ void ldsm_x2(uint32_t& r0, uint32_t& r1, uint32_t addr) {
    asm volatile("ldmatrix.sync.aligned.m8n8.x2.shared.b16 {%0,%1}, [%2];"
                 : "=r"(r0), "=r"(r1) : "r"(addr));
}

// mainloop shared by both fused GEMMs; leaves acc[4][4][4] filled.
#define GEMM_MAINLOOP(A, B, K)                                                         \
    const int tid = threadIdx.x;                                                       \
    const int wid = tid >> 5, lane = tid & 31;                                         \
    const int wm = wid & 1, wn = wid >> 1;                                             \
    const int tr = lane >> 2, tc = lane & 3;                                           \
    const int bm = blockIdx.y * 128, bn = blockIdx.x * 128;                            \
    const int NT = (K) / BKK;                                                          \
    const uint32_t smb = smem_u32(smh);                                                \
    const int aRow = wm * 64 + (lane & 7) + ((lane >> 3) & 1) * 8;                     \
    const int aKh  = (lane >> 4) * 8;                                                  \
    const uint32_t aBase = smb + aRow * (PADH * 2) + aKh * 2;                          \
    const int lB   = lane & 15;                                                        \
    const int bRow = wn * 32 + (lB & 7);                                               \
    const int bKh  = (lB >> 3) * 8;                                                    \
    const uint32_t bBase = smb + ATILE_H * 2 + bRow * (PADH * 2) + bKh * 2;            \
    float acc[4][4][4];                                                                \
    _Pragma("unroll") for (int mt = 0; mt < 4; mt++)                                   \
        _Pragma("unroll") for (int nt = 0; nt < 4; nt++)                               \
            _Pragma("unroll") for (int r = 0; r < 4; r++) acc[mt][nt][r] = 0.0f;       \
    _Pragma("unroll") for (int s = 0; s < GSTAGES - 1; ++s) {                          \
        uint32_t sa = smb + s * (STAGE_H * 2);                                         \
        uint32_t sb = sa + ATILE_H * 2;                                                \
        int kbase = s * BKK;                                                           \
        _Pragma("unroll") for (int j = 0; j < 2; ++j) {                                \
            int c = tid + j * 256;                                                     \
            int row = c >> 2, kc = c & 3;                                              \
            uint32_t soff = row * (PADH * 2) + kc * 16;                                \
            cp_async16(sa + soff, (A) + (size_t)(bm + row) * (K) + kbase + kc * 8);    \
            cp_async16(sb + soff, (B) + (size_t)(bn + row) * (K) + kbase + kc * 8);    \
        }                                                                              \
        asm volatile("cp.async.commit_group;" ::: "memory");                           \
    }                                                                                  \
    for (int kt = 0; kt < NT; ++kt) {                                                  \
        asm volatile("cp.async.wait_group %0;" :: "n"(GSTAGES - 2) : "memory");        \
        __syncthreads();                                                               \
        {                                                                              \
            int tl = kt + GSTAGES - 1;                                                 \
            if (tl < NT) {                                                             \
                int s = tl % GSTAGES;                                                  \
                uint32_t sa = smb + s * (STAGE_H * 2);                                 \
                uint32_t sb = sa + ATILE_H * 2;                                        \
                int kbase = tl * BKK;                                                  \
                _Pragma("unroll") for (int j = 0; j < 2; ++j) {                        \
                    int c = tid + j * 256;                                             \
                    int row = c >> 2, kc = c & 3;                                      \
                    uint32_t soff = row * (PADH * 2) + kc * 16;                        \
                    cp_async16(sa + soff, (A) + (size_t)(bm + row) * (K) + kbase + kc * 8); \
                    cp_async16(sb + soff, (B) + (size_t)(bn + row) * (K) + kbase + kc * 8); \
                }                                                                      \
            }                                                                          \
            asm volatile("cp.async.commit_group;" ::: "memory");                       \
        }                                                                              \
        const uint32_t stOff = (uint32_t)(kt % GSTAGES) * (STAGE_H * 2);               \
        _Pragma("unroll") for (int ks = 0; ks < 2; ++ks) {                             \
            uint32_t af[4][4];                                                         \
            _Pragma("unroll") for (int mt = 0; mt < 4; mt++)                           \
                ldsm_x4(af[mt][0], af[mt][1], af[mt][2], af[mt][3],                    \
                        aBase + stOff + mt * (16 * PADH * 2) + ks * 32);               \
            uint32_t bf[4][2];                                                         \
            _Pragma("unroll") for (int nt = 0; nt < 4; nt++)                           \
                ldsm_x2(bf[nt][0], bf[nt][1],                                          \
                        bBase + stOff + nt * (8 * PADH * 2) + ks * 32);                \
            _Pragma("unroll") for (int mt = 0; mt < 4; mt++)                           \
                _Pragma("unroll") for (int nt = 0; nt < 4; nt++)                       \
                    mma_f16(acc[mt][nt], af[mt][0], af[mt][1], af[mt][2], af[mt][3],   \
                            bf[nt][0], bf[nt][1]);                                     \
        }                                                                              \
        __syncthreads();                                                               \
    }

// ---------------- key GEMM + fused energy (skips fully-masked tiles) ----------------
__global__ __launch_bounds__(256, 2)
void gemm_key_energy(const __half* __restrict__ A, const __half* __restrict__ B,
                     const float* __restrict__ bias, const float* __restrict__ q,
                     const float* __restrict__ gen_w, const int* __restrict__ enc_len) {
    extern __shared__ __half smh[];
    {
        int b0 = (int)(blockIdx.y >> 4);
        int t0 = (int)(blockIdx.y & 15) * 128;
        if (t0 >= enc_len[b0]) return;
    }
    GEMM_MAINLOOP(A, B, VDIM)

    const int b = bm >> 11;
    const int len = enc_len[b];
    const int h = bn >> 9;
    const int dbase = (bn & 511) + wn * 32;

    float qv[8], wv[8], bv8[8];
    #pragma unroll
    for (int nt = 0; nt < 4; nt++)
        #pragma unroll
        for (int u = 0; u < 2; u++) {
            int d = dbase + nt * 8 + tc * 2 + u;
            int n = (h << 9) + d;
            qv[nt*2+u]  = __ldg(q + b * NKV + n);
            wv[nt*2+u]  = __ldg(gen_w + d);
            bv8[nt*2+u] = __ldg(bias + n);
        }

    float rowsum[8];
    #pragma unroll
    for (int i = 0; i < 8; i++) rowsum[i] = 0.0f;

    #pragma unroll
    for (int mt = 0; mt < 4; mt++) {
        #pragma unroll
        for (int half = 0; half < 2; half++) {
            int r = bm + wm * 64 + mt * 16 + tr + half * 8;
            int t = r & (TS - 1);
            const float* locp = g_locc + (size_t)(b * LROWS + idx_t(t, len)) * DIM + dbase;
            float s = 0.0f;
            #pragma unroll
            for (int nt = 0; nt < 4; nt++)
                #pragma unroll
                for (int u = 0; u < 2; u++) {
                    float kk = fast_tanh(acc[mt][nt][half*2+u] + bv8[nt*2+u]);
                    float lv = locp[nt * 8 + tc * 2 + u];
                    s += wv[nt*2+u] * fast_tanh(kk + qv[nt*2+u] + lv);
                }
            rowsum[mt*2+half] = s;
        }
    }
    #pragma unroll
    for (int i = 0; i < 8; i++) {
        rowsum[i] += __shfl_xor_sync(0xffffffffu, rowsum[i], 1);
        rowsum[i] += __shfl_xor_sync(0xffffffffu, rowsum[i], 2);
    }
    if (tc == 0) {
        #pragma unroll
        for (int mt = 0; mt < 4; mt++)
            #pragma unroll
            for (int half = 0; half < 2; half++) {
                int r = bm + wm * 64 + mt * 16 + tr + half * 8;
                int t = r & (TS - 1);
                atomicAdd(&g_energy[(b * NH + h) * TS + t], rowsum[mt*2+half]);
            }
    }
}

// ---------------- value GEMM + fused context (skips fully-masked tiles) ----------------
__global__ __launch_bounds__(256, 2)
void gemm_val_ctx(const __half* __restrict__ A, const __half* __restrict__ B,
                  const float* __restrict__ bias, const float* __restrict__ attn,
                  const int* __restrict__ enc_len) {
    extern __shared__ __half smh[];
    {
        int b0 = (int)(blockIdx.y >> 4);
        int t0 = (int)(blockIdx.y & 15) * 128;
        if (t0 >= enc_len[b0]) return;
    }
    GEMM_MAINLOOP(A, B, VDIM)

    const int b = bm >> 11;
    const int h = bn >> 9;
    const int dbase = (bn & 511) + wn * 32;

    float bv8[8];
    #pragma unroll
    for (int nt = 0; nt < 4; nt++)
        #pragma unroll
        for (int u = 0; u < 2; u++)
            bv8[nt*2+u] = __ldg(bias + (h << 9) + dbase + nt * 8 + tc * 2 + u);

    float colsum[8];
    #pragma unroll
    for (int i = 0; i < 8; i++) colsum[i] = 0.0f;

    #pragma unroll
    for (int mt = 0; mt < 4; mt++) {
        #pragma unroll
        for (int half = 0; half < 2; half++) {
            int r = bm + wm * 64 + mt * 16 + tr + half * 8;
            int t = r & (TS - 1);
            float a_t = __ldg(attn + (b * NH + h) * TS + t);
            #pragma unroll
            for (int nt = 0; nt < 4; nt++)
                #pragma unroll
                for (int u = 0; u < 2; u++)
                    colsum[nt*2+u] += a_t * fast_tanh(acc[mt][nt][half*2+u] + bv8[nt*2+u]);
        }
    }
    #pragma unroll
    for (int i = 0; i < 8; i++) {
        colsum[i] += __shfl_xor_sync(0xffffffffu, colsum[i], 4);
        colsum[i] += __shfl_xor_sync(0xffffffffu, colsum[i], 8);
        colsum[i] += __shfl_xor_sync(0xffffffffu, colsum[i], 16);
    }
    if (tr == 0) {
        #pragma unroll
        for (int nt = 0; nt < 4; nt++)
            #pragma unroll
            for (int u = 0; u < 2; u++)
                atomicAdd(&g_ctx[(b * NH + h) * VDIM + dbase + nt * 8 + tc * 2 + u],
                          colsum[nt*2+u]);
    }
}

// ---------------- masked softmax (applies (x+gb)/TEMP) ----------------
__global__ void softmax_kernel(const int* __restrict__ enc_len, float* __restrict__ attn,
                               const float* __restrict__ gen_b) {
    __shared__ float red[8];
    __shared__ float bcast;
    int bh = blockIdx.x;
    int b = bh >> 2;
    int len = enc_len[b];
    float gb = gen_b[0];
    const float* e = g_energy + bh * TS;
    float* a = attn + bh * TS;
    int tid = threadIdx.x, lane = tid & 31, w = tid >> 5;

    float m = -INFINITY;
    for (int t = tid; t < len; t += 256) m = fmaxf(m, (e[t] + gb) * (1.0f / TEMP));
    #pragma unroll
    for (int o = 16; o; o >>= 1) m = fmaxf(m, __shfl_xor_sync(0xffffffffu, m, o));
    if (!lane) red[w] = m;
    __syncthreads();
    if (tid < 8) {
        float x = red[tid];
        #pragma unroll
        for (int o = 4; o; o >>= 1) x = fmaxf(x, __shfl_xor_sync(0xffu, x, o));
        if (!tid) bcast = x;
    }
    __syncthreads();
    m = bcast;
    __syncthreads();

    float s = 0.0f;
    for (int t = tid; t < len; t += 256) s += expf((e[t] + gb) * (1.0f / TEMP) - m);
    #pragma unroll
    for (int o = 16; o; o >>= 1) s += __shfl_xor_sync(0xffffffffu, s, o);
    if (!lane) red[w] = s;
    __syncthreads();
    if (tid < 8) {
        float x = red[tid];
        #pragma unroll
        for (int o = 4; o; o >>= 1) x += __shfl_xor_sync(0xffu, x, o);
        if (!tid) bcast = x;
    }
    __syncthreads();
    float inv = 1.0f / bcast;
    for (int t = tid; t < TS; t += 256)
        a[t] = (t < len) ? expf((e[t] + gb) * (1.0f / TEMP) - m) * inv : 0.0f;
}

// ---------------- merge projection (float4 vectorized) ----------------
__global__ void merge_kernel(const float* __restrict__ Wm, const float* __restrict__ bm,
                             float* __restrict__ out) {
    int gw = (blockIdx.x * blockDim.x + threadIdx.x) >> 5;
    int lane = threadIdx.x & 31;
    if (gw >= BS * VDIM) return;
    int b = gw >> 9, j = gw & (VDIM - 1);
    const float4* x4 = (const float4*)(g_ctx + b * (NH * VDIM));
    const float4* w4 = (const float4*)(Wm + (size_t)j * (NH * VDIM));
    float acc = 0.0f;
    #pragma unroll
    for (int k = lane; k < (NH * VDIM) / 4; k += 32) {
        float4 xv = x4[k];
        float4 wv = __ldg(w4 + k);
        acc += xv.x * wv.x + xv.y * wv.y + xv.z * wv.z + xv.w * wv.w;
    }
    #pragma unroll
    for (int o = 16; o; o >>= 1) acc += __shfl_xor_sync(0xffffffffu, acc, o);
    if (!lane) out[gw] = acc + bm[j];
}

// ---------------- launch ----------------
extern "C" void kernel_launch(void* const* d_in, const int* in_sizes, int n_in,
                              void* d_out, int out_size) {
    const float* dec_state  = (const float*)d_in[0];
    const float* enc_feat   = (const float*)d_in[1];
    const int*   enc_len    = (const int*)  d_in[2];
    const float* Wq         = (const float*)d_in[3];
    const float* bq         = (const float*)d_in[4];
    const float* Wk         = (const float*)d_in[5];
    const float* bk         = (const float*)d_in[6];
    const float* Wv         = (const float*)d_in[7];
    const float* bv         = (const float*)d_in[8];
    const float* loc_conv_w = (const float*)d_in[9];
    const float* loc_proj_w = (const float*)d_in[10];
    const float* gen_w      = (const float*)d_in[11];
    const float* gen_b      = (const float*)d_in[12];
    const float* merge_w    = (const float*)d_in[13];
    const float* merge_b    = (const float*)d_in[14];

    float* out = (float*)d_out;
    float* out_attn = out;                       // [8,4,2048]
    float* out_ctx  = out + BS * NH * TS;        // [8,512]

    static float *pP = nullptr, *pQ = nullptr, *pConvr = nullptr, *pG = nullptr;
    static __half *pAh = nullptr, *pBkh = nullptr, *pBvh = nullptr;
    static cudaStream_t sB = nullptr, sC = nullptr;
    static cudaEvent_t evRoot = nullptr, evB1 = nullptr, evB2 = nullptr, evC = nullptr;
    if (!pP) {
        cudaGetSymbolAddress((void**)&pP,     g_P);
        cudaGetSymbolAddress((void**)&pQ,     g_q);
        cudaGetSymbolAddress((void**)&pConvr, g_convr);
        cudaGetSymbolAddress((void**)&pG,     g_G);
        cudaGetSymbolAddress((void**)&pAh,    g_Ah);
        cudaGetSymbolAddress((void**)&pBkh,   g_Bkh);
        cudaGetSymbolAddress((void**)&pBvh,   g_Bvh);
        cudaFuncSetAttribute(gemm_key_energy, cudaFuncAttributeMaxDynamicSharedMemorySize, GSMEM_BYTES);
        cudaFuncSetAttribute(gemm_val_ctx,    cudaFuncAttributeMaxDynamicSharedMemorySize, GSMEM_BYTES);
        cudaStreamCreateWithFlags(&sB, cudaStreamNonBlocking);
        cudaStreamCreateWithFlags(&sC, cudaStreamNonBlocking);
        cudaEventCreateWithFlags(&evRoot, cudaEventDisableTiming);
        cudaEventCreateWithFlags(&evB1, cudaEventDisableTiming);
        cudaEventCreateWithFlags(&evB2, cudaEventDisableTiming);
        cudaEventCreateWithFlags(&evC, cudaEventDisableTiming);
    }

    // ---- fork: three independent prologue branches ----
    cudaEventRecord(evRoot, 0);
    cudaStreamWaitEvent(sB, evRoot, 0);
    cudaStreamWaitEvent(sC, evRoot, 0);

    // branch B (sB): A conversion -> Wk conversion -> evB1 -> Wv conversion -> evB2
    {
        int nA4 = MDIM * VDIM / 4;
        f16_conv_kernel<<<(nA4 + 255) / 256, 256, 0, sB>>>((const float4*)enc_feat, (__half2*)pAh, nA4);
        int nB4 = NKV * VDIM / 4;
        f16_conv_kernel<<<(nB4 + 255) / 256, 256, 0, sB>>>((const float4*)Wk, (__half2*)pBkh, nB4);
        cudaEventRecord(evB1, sB);
        f16_conv_kernel<<<(nB4 + 255) / 256, 256, 0, sB>>>((const float4*)Wv, (__half2*)pBvh, nB4);
        cudaEventRecord(evB2, sB);
    }

    // branch C (sC): query projection
    {
        query_kernel<<<(BS * NKV * 32 + 255) / 256, 256, 0, sC>>>(dec_state, Wq, bq, pQ);
        cudaEventRecord(evC, sC);
    }

    // main stream: loc path (prefix -> batch-indep conv + zero -> G GEMM -> expand)
    prefix_kernel<<<1, 128>>>(loc_conv_w, pP);
    convr_kernel<<<(BS * NH * TS + 255) / 256, 256>>>(pConvr);
    {
        dim3 gl(DIM / 64, LROWS / 64);
        gemm_raw64<<<gl, 256>>>(pConvr, loc_proj_w, pG, LROWS, DIM, KN);
    }
    loc_expand_kernel<<<(BS * LROWS * DIM / 4 + 255) / 256, 256>>>(enc_len);

    // ---- join for key GEMM (needs A, Wk, q, loc — NOT Wv) ----
    cudaStreamWaitEvent(0, evB1, 0);
    cudaStreamWaitEvent(0, evC, 0);
    {
        dim3 gk(NKV / 128, MDIM / 128);
        gemm_key_energy<<<gk, 256, GSMEM_BYTES>>>(pAh, pBkh, bk, pQ, gen_w, enc_len);
    }

    // softmax -> attn (d_out)
    softmax_kernel<<<BS * NH, 256>>>(enc_len, out_attn, gen_b);

    // value GEMM (additionally needs Wv conversion)
    cudaStreamWaitEvent(0, evB2, 0);
    {
        dim3 gk(NKV / 128, MDIM / 128);
        gemm_val_ctx<<<gk, 256, GSMEM_BYTES>>>(pAh, pBvh, bv, out_attn, enc_len);
    }

    // merge
    merge_kernel<<<(BS * VDIM * 32 + 255) / 256, 256>>>(merge_w, merge_b, out_ctx);
}